// round 16
// baseline (speedup 1.0000x reference)
#include <cuda_runtime.h>
#include <cuda_bf16.h>
#include <cuda_fp16.h>
#include <cstdint>

// ---------------------------------------------------------------------------
// Problem constants
#define N_ROWS   32768          // B*H*W*L = 8*16*16*16
#define K_CODES  1024
#define D_DIM    256
#define S_SZ     4096
#define QUANT_ELEMS 8388608     // 8*256*4096

// GEMM tiling (R10 proven config): CTA 128x128, 8 warps, warp tile 32x64
#define BM 128
#define BKN 128
#define KC 64                   // bf16 k-chunk (128 bytes/row)

// smem layout (dynamic): A0 | B0 | A1 | B1 | bnorm | sabs | pmin
#define TILE_BYTES 16384        // 128 rows x 128B
#define SM_BNORM   65536        // 128 floats
#define SM_SABS    66048        // 128 floats
#define SM_PMIN    66560        // 128 x 2 floats
#define SM_TOTAL   67584

// candidate list
#define CAP 32

// gather tiling
#define GD 32
#define GS 128

// ---------------------------------------------------------------------------
// Scratch (__device__ globals; no runtime allocation)
__device__ __nv_bfloat16 g_zbf[N_ROWS * D_DIM];      // z transposed (n,d) bf16
__device__ float  g_zt[N_ROWS * D_DIM];              // z transposed (n,d) fp32
__device__ __nv_bfloat16 g_cbbf[K_CODES * D_DIM];    // codebook bf16
__device__ int    g_cand[N_ROWS * CAP];              // candidate code ids (4 MB)
__device__ int    g_cnt[N_ROWS];                     // candidate counts
__device__ float  g_a[N_ROWS];                       // ||z_n||^2 (sequential-d fmaf!)
__device__ float  g_sabs[N_ROWS];                    // sum_d |z_nd|
__device__ float  g_b[K_CODES];                      // ||e_k||^2
__device__ int    g_idx[N_ROWS];                     // final indices
__device__ double g_part[2048];                      // loss partials

// ---------------------------------------------------------------------------
__device__ __forceinline__ uint32_t smem_u32(const void* p) {
    uint32_t a;
    asm("{ .reg .u64 t; cvta.to.shared.u64 t, %1; cvt.u32.u64 %0, t; }" : "=r"(a) : "l"(p));
    return a;
}
#define SW128(o) ((o) ^ (((o) >> 3) & 0x70))

__device__ __forceinline__ void cp16(uint32_t saddr, const void* gaddr) {
    asm volatile("cp.async.cg.shared.global [%0], [%1], 16;" :: "r"(saddr), "l"(gaddr));
}
#define CP_COMMIT() asm volatile("cp.async.commit_group;")
#define CP_WAIT(n)  asm volatile("cp.async.wait_group %0;" :: "n"(n))

__device__ __forceinline__ void ldsm_x4(uint32_t* r, uint32_t saddr) {
    asm volatile("ldmatrix.sync.aligned.m8n8.x4.shared.b16 {%0,%1,%2,%3}, [%4];"
                 : "=r"(r[0]), "=r"(r[1]), "=r"(r[2]), "=r"(r[3]) : "r"(saddr));
}
__device__ __forceinline__ void mma_bf16(float* c, const uint32_t* a, uint32_t b0, uint32_t b1) {
    asm volatile("mma.sync.aligned.m16n8k16.row.col.f32.bf16.bf16.f32 "
                 "{%0,%1,%2,%3}, {%4,%5,%6,%7}, {%8,%9}, {%0,%1,%2,%3};"
                 : "+f"(c[0]), "+f"(c[1]), "+f"(c[2]), "+f"(c[3])
                 : "r"(a[0]), "r"(a[1]), "r"(a[2]), "r"(a[3]), "r"(b0), "r"(b1));
}

__device__ __forceinline__ uint32_t pack_bf16x2(float lo, float hi) {
    __nv_bfloat162 t = __floats2bfloat162_rn(lo, hi);
    uint32_t u;
    memcpy(&u, &t, 4);
    return u;
}

// ---------------------------------------------------------------------------
// 1) Codebook: bf16 convert + ||e_k||^2, warp per row.
__global__ void prep_cbnorm_kernel(const float* __restrict__ cb) {
    int w = blockIdx.x * 8 + (threadIdx.x >> 5);
    int lane = threadIdx.x & 31;
    const float* p = cb + (size_t)w * D_DIM + lane * 8;
    float4 v0 = *(const float4*)p;
    float4 v1 = *(const float4*)(p + 4);
    uint4 packed;
    packed.x = pack_bf16x2(v0.x, v0.y);
    packed.y = pack_bf16x2(v0.z, v0.w);
    packed.z = pack_bf16x2(v1.x, v1.y);
    packed.w = pack_bf16x2(v1.z, v1.w);
    *(uint4*)(g_cbbf + (size_t)w * D_DIM + lane * 8) = packed;
    float acc = 0.0f;
    acc = fmaf(v0.x, v0.x, acc); acc = fmaf(v0.y, v0.y, acc);
    acc = fmaf(v0.z, v0.z, acc); acc = fmaf(v0.w, v0.w, acc);
    acc = fmaf(v1.x, v1.x, acc); acc = fmaf(v1.y, v1.y, acc);
    acc = fmaf(v1.z, v1.z, acc); acc = fmaf(v1.w, v1.w, acc);
    #pragma unroll
    for (int off = 16; off > 0; off >>= 1)
        acc += __shfl_xor_sync(0xffffffffu, acc, off);
    if (lane == 0) g_b[w] = acc;
}

// ---------------------------------------------------------------------------
// 2) Fused: transpose z -> (n,d) fp32 + bf16, per-row sequential norms,
//    zero candidate counters.
__global__ void __launch_bounds__(256)
prep_z_kernel(const float* __restrict__ z) {
    __shared__ float tile[32][257];                 // [s][d], bank(s+d)
    int x = threadIdx.x & 31, y = threadIdx.x >> 5; // lane, warp
    int s0 = blockIdx.x * 32;
    int b  = blockIdx.y;
    const float* zb = z + (size_t)b * (D_DIM * S_SZ) + s0;
    #pragma unroll 8
    for (int i = 0; i < 32; i++) {
        int d = y + 8 * i;
        tile[x][d] = zb[(size_t)d * S_SZ + x];
    }
    __syncthreads();
    #pragma unroll
    for (int rr = 0; rr < 4; rr++) {
        int r = y * 4 + rr;
        size_t n = (size_t)(b * S_SZ + s0 + r);
        #pragma unroll
        for (int c = 0; c < 8; c++) {
            int d = c * 32 + x;
            float v = tile[r][d];
            g_zt[n * D_DIM + d]  = v;
            g_zbf[n * D_DIM + d] = __float2bfloat16(v);
        }
    }
    if (threadIdx.x < 32) {
        int r = threadIdx.x;
        float acc = 0.0f, sab = 0.0f;
        #pragma unroll 8
        for (int d = 0; d < D_DIM; d++) {
            float v = tile[r][d];
            acc = fmaf(v, v, acc);
            sab += fabsf(v);
        }
        int n = b * S_SZ + s0 + r;
        g_a[n] = acc;
        g_sabs[n] = sab;
        g_cnt[n] = 0;
    }
}

// ---------------------------------------------------------------------------
// 3) HMMA bf16 GEMM + tile-local candidate emission (NO score matrix).
//    Safe superset: any global candidate in this k-tile has
//    s <= tile_min + 2*E_gemm + slack.
__global__ void __launch_bounds__(256, 2)
mma_kernel() {
    extern __shared__ char smem[];
    uint32_t sb = smem_u32(smem);
    int tid  = threadIdx.x;
    int wid  = tid >> 5, lane = tid & 31;
    int wm   = wid & 3;              // 0..3  (32-row slice)
    int wn   = wid >> 2;             // 0..1  (64-col slice)
    int n0   = blockIdx.x * BM;
    int k0   = blockIdx.y * BKN;

    float* bsh     = (float*)(smem + SM_BNORM);   // code norms (this k-tile)
    float* sabs_sm = (float*)(smem + SM_SABS);    // row abs-sums
    float* pmin    = (float*)(smem + SM_PMIN);    // [128][2] row-tile mins
    if (tid < BKN) {
        bsh[tid]     = g_b[k0 + tid];
        sabs_sm[tid] = g_sabs[n0 + tid];
    }

    int lrow = tid >> 1;
    int lseg0 = (tid & 1) * 4;
    auto load_chunk = [&](int buf, int c) {
        uint32_t abase = sb + buf * 32768;
        uint32_t bbase = abase + TILE_BYTES;
        const __nv_bfloat16* ag = g_zbf  + (size_t)(n0 + lrow) * D_DIM + c * KC;
        const __nv_bfloat16* bg = g_cbbf + (size_t)(k0 + lrow) * D_DIM + c * KC;
        #pragma unroll
        for (int i = 0; i < 4; i++) {
            int seg = lseg0 + i;
            uint32_t soff = SW128(lrow * 128 + seg * 16);
            cp16(abase + soff, ag + seg * 8);
            cp16(bbase + soff, bg + seg * 8);
        }
    };

    float C[2][8][4];
    #pragma unroll
    for (int mf = 0; mf < 2; mf++)
        #pragma unroll
        for (int nf = 0; nf < 8; nf++)
            #pragma unroll
            for (int q = 0; q < 4; q++) C[mf][nf][q] = 0.0f;

    load_chunk(0, 0);
    CP_COMMIT();

    int lr = lane & 15;
    int lh = lane >> 4;

    for (int c = 0; c < 4; c++) {
        if (c < 3) { load_chunk((c + 1) & 1, c + 1); CP_COMMIT(); }
        if (c < 3) { CP_WAIT(1); } else { CP_WAIT(0); }
        __syncthreads();

        uint32_t abase = sb + (c & 1) * 32768;
        uint32_t bbase = abase + TILE_BYTES;

        #pragma unroll
        for (int ks = 0; ks < 4; ks++) {
            uint32_t a[2][4], bq[4][4];
            #pragma unroll
            for (int mf = 0; mf < 2; mf++) {
                int r = wm * 32 + mf * 16 + lr;
                ldsm_x4(a[mf], abase + SW128(r * 128 + (2 * ks + lh) * 16));
            }
            #pragma unroll
            for (int nf2 = 0; nf2 < 4; nf2++) {
                int r = wn * 64 + nf2 * 16 + lr;
                ldsm_x4(bq[nf2], bbase + SW128(r * 128 + (2 * ks + lh) * 16));
            }
            #pragma unroll
            for (int mf = 0; mf < 2; mf++)
                #pragma unroll
                for (int nf2 = 0; nf2 < 4; nf2++) {
                    mma_bf16(C[mf][2 * nf2],     a[mf], bq[nf2][0], bq[nf2][2]);
                    mma_bf16(C[mf][2 * nf2 + 1], a[mf], bq[nf2][1], bq[nf2][3]);
                }
        }
        __syncthreads();
    }

    // Epilogue pass 1: per-row min over this warp's 64-col half.
    int gq = lane >> 2;
    int qc = (lane & 3) * 2;
    #pragma unroll
    for (int mf = 0; mf < 2; mf++) {
        int rl = wm * 32 + mf * 16 + gq;              // local row
        float m0 = 1e30f, m1 = 1e30f;
        #pragma unroll
        for (int nf = 0; nf < 8; nf++) {
            int colL = wn * 64 + nf * 8 + qc;
            float b0v = bsh[colL], b1v = bsh[colL + 1];
            m0 = fminf(m0, fminf(b0v - 2.0f * C[mf][nf][0], b1v - 2.0f * C[mf][nf][1]));
            m1 = fminf(m1, fminf(b0v - 2.0f * C[mf][nf][2], b1v - 2.0f * C[mf][nf][3]));
        }
        m0 = fminf(m0, __shfl_xor_sync(0xffffffffu, m0, 1));
        m0 = fminf(m0, __shfl_xor_sync(0xffffffffu, m0, 2));
        m1 = fminf(m1, __shfl_xor_sync(0xffffffffu, m1, 1));
        m1 = fminf(m1, __shfl_xor_sync(0xffffffffu, m1, 2));
        if ((lane & 3) == 0) {
            pmin[rl * 2 + wn]       = m0;
            pmin[(rl + 8) * 2 + wn] = m1;
        }
    }
    __syncthreads();

    // Epilogue pass 2: emit candidates (s <= tile_min + margin).
    #pragma unroll
    for (int mf = 0; mf < 2; mf++) {
        int rl = wm * 32 + mf * 16 + gq;
        float th0 = fminf(pmin[rl * 2],       pmin[rl * 2 + 1])
                    + 1.6e-5f * sabs_sm[rl]       + 7.0e-4f;
        float th1 = fminf(pmin[(rl + 8) * 2], pmin[(rl + 8) * 2 + 1])
                    + 1.6e-5f * sabs_sm[rl + 8]   + 7.0e-4f;
        int n0r = n0 + rl;
        #pragma unroll
        for (int nf = 0; nf < 8; nf++) {
            int colL = wn * 64 + nf * 8 + qc;
            int kk = k0 + colL;
            float b0v = bsh[colL], b1v = bsh[colL + 1];
            float s00 = b0v - 2.0f * C[mf][nf][0];
            float s01 = b1v - 2.0f * C[mf][nf][1];
            float s10 = b0v - 2.0f * C[mf][nf][2];
            float s11 = b1v - 2.0f * C[mf][nf][3];
            if (s00 <= th0) {
                int pos = atomicAdd(&g_cnt[n0r], 1);
                if (pos < CAP) g_cand[(size_t)n0r * CAP + pos] = kk;
            }
            if (s01 <= th0) {
                int pos = atomicAdd(&g_cnt[n0r], 1);
                if (pos < CAP) g_cand[(size_t)n0r * CAP + pos] = kk + 1;
            }
            if (s10 <= th1) {
                int pos = atomicAdd(&g_cnt[n0r + 8], 1);
                if (pos < CAP) g_cand[(size_t)(n0r + 8) * CAP + pos] = kk;
            }
            if (s11 <= th1) {
                int pos = atomicAdd(&g_cnt[n0r + 8], 1);
                if (pos < CAP) g_cand[(size_t)(n0r + 8) * CAP + pos] = kk + 1;
            }
        }
    }
}

// ---------------------------------------------------------------------------
// 4) Select: exact fp32 rescore of the candidate list. Warp per row.
//    Overflow (cnt > CAP, expected never): exact full scan of all 1024 codes.
__global__ void __launch_bounds__(256)
select_kernel(const float* __restrict__ cb, float* __restrict__ out_idx) {
    int w = threadIdx.x >> 5, lane = threadIdx.x & 31;
    int n = blockIdx.x * 8 + w;

    const float* zp = g_zt + (size_t)n * D_DIM + lane * 8;
    float4 z0 = *(const float4*)zp;
    float4 z1 = *(const float4*)(zp + 4);
    float a = g_a[n];
    int cnt = g_cnt[n];

    unsigned long long best = ~0ULL;
    auto rescore = [&](int kc) {
        const float* ep = cb + (size_t)kc * D_DIM + lane * 8;
        float4 e0 = *(const float4*)ep;
        float4 e1 = *(const float4*)(ep + 4);
        float acc = 0.0f;
        acc = fmaf(z0.x, e0.x, acc); acc = fmaf(z0.y, e0.y, acc);
        acc = fmaf(z0.z, e0.z, acc); acc = fmaf(z0.w, e0.w, acc);
        acc = fmaf(z1.x, e1.x, acc); acc = fmaf(z1.y, e1.y, acc);
        acc = fmaf(z1.z, e1.z, acc); acc = fmaf(z1.w, e1.w, acc);
        #pragma unroll
        for (int off = 16; off > 0; off >>= 1)
            acc += __shfl_xor_sync(0xffffffffu, acc, off);
        float tsum = a + g_b[kc];                // fl(a + b)
        float dv = tsum - 2.0f * acc;            // fl(t - 2c)
        unsigned long long p =
            ((unsigned long long)__float_as_uint(dv) << 32) | (unsigned)kc;
        best = min(best, p);
    };

    if (cnt <= CAP) {
        const int* cl = g_cand + (size_t)n * CAP;
        for (int i = 0; i < cnt; i++) rescore(cl[i]);
    } else {
        for (int kc = 0; kc < K_CODES; kc++) rescore(kc);
    }

    if (lane == 0) {
        int kk = (int)(unsigned)(best & 0xFFFFFFFFULL);
        g_idx[n] = kk;
        out_idx[n] = (float)kk;
    }
}

// ---------------------------------------------------------------------------
// 5) Tiled gather (R15 form): coalesced cb row-segments -> smem transpose,
//    coalesced z/out over s.
__global__ void __launch_bounds__(256)
gather_loss_kernel(const float* __restrict__ z,
                   const float* __restrict__ cb,
                   float* __restrict__ out_q) {
    __shared__ float qt[GS][GD + 1];
    __shared__ int   ks[GS];
    __shared__ float ws[8];
    int tid = threadIdx.x;
    int w = tid >> 5, lane = tid & 31;
    int st = blockIdx.x;
    int dt = blockIdx.y;
    int b  = blockIdx.z;
    int s0 = st * GS, d0 = dt * GD;

    if (tid < GS) ks[tid] = g_idx[b * S_SZ + s0 + tid];
    __syncthreads();

    #pragma unroll
    for (int i = 0; i < 16; i++) {
        int si = w * 16 + i;
        int k = ks[si];
        qt[si][lane] = cb[(size_t)k * D_DIM + d0 + lane];
    }
    __syncthreads();

    float part = 0.0f;
    #pragma unroll
    for (int i = 0; i < 16; i++) {
        int elem = i * 256 + tid;
        int d = elem >> 7, s = elem & 127;
        size_t gidx = (size_t)b * (D_DIM * S_SZ) + (size_t)(d0 + d) * S_SZ + s0 + s;
        float zv = z[gidx];
        float q  = qt[s][d];
        float diff = q - zv;
        out_q[gidx] = zv + diff;
        part = fmaf(diff, diff, part);
    }

    #pragma unroll
    for (int off = 16; off > 0; off >>= 1)
        part += __shfl_down_sync(0xffffffffu, part, off);
    if (lane == 0) ws[w] = part;
    __syncthreads();
    if (tid == 0) {
        double s8 = 0.0;
        #pragma unroll
        for (int i = 0; i < 8; i++) s8 += (double)ws[i];
        int bid = blockIdx.x + 32 * (blockIdx.y + 8 * blockIdx.z);
        g_part[bid] = s8;
    }
}

__global__ void finalize_loss_kernel(float* __restrict__ out_loss) {
    __shared__ double ws[256];
    double acc = 0.0;
    for (int i = threadIdx.x; i < 2048; i += 256) acc += g_part[i];
    ws[threadIdx.x] = acc;
    __syncthreads();
    for (int off = 128; off > 0; off >>= 1) {
        if (threadIdx.x < off) ws[threadIdx.x] += ws[threadIdx.x + off];
        __syncthreads();
    }
    if (threadIdx.x == 0) {
        double mse = ws[0] / (double)QUANT_ELEMS;
        out_loss[0] = (float)(1.25 * mse);
    }
}

// ---------------------------------------------------------------------------
extern "C" void kernel_launch(void* const* d_in, const int* in_sizes, int n_in,
                              void* d_out, int out_size) {
    const float* z  = (const float*)d_in[0];
    const float* cb = (const float*)d_in[1];
    float* out      = (float*)d_out;
    float* out_q    = out;
    float* out_idx  = out + QUANT_ELEMS;
    float* out_loss = out + QUANT_ELEMS + N_ROWS;

    cudaFuncSetAttribute(mma_kernel, cudaFuncAttributeMaxDynamicSharedMemorySize, SM_TOTAL);

    prep_cbnorm_kernel<<<K_CODES / 8, 256>>>(cb);
    prep_z_kernel<<<dim3(S_SZ / 32, 8), 256>>>(z);
    mma_kernel<<<dim3(N_ROWS / BM, K_CODES / BKN), 256, SM_TOTAL>>>();
    select_kernel<<<N_ROWS / 8, 256>>>(cb, out_idx);
    gather_loss_kernel<<<dim3(S_SZ / GS, D_DIM / GD, 8), 256>>>(z, cb, out_q);
    finalize_loss_kernel<<<1, 256>>>(out_loss);
}